// round 15
// baseline (speedup 1.0000x reference)
#include <cuda_runtime.h>
#include <cuda_bf16.h>
#include <cuda_fp16.h>
#include <cstdint>

#define NN_MAX 50000
#define NE_MAX 800000
#define HID 128

// ---------------- scratch (device globals) ----------------
__device__ int    g_deg[NN_MAX];
__device__ int    g_off[NN_MAX + 1];
__device__ int    g_cursor[NN_MAX];
__device__ int    g_adj[NE_MAX];
__device__ float  g_dinv[NN_MAX];
__device__ __half g_ht[NN_MAX * HID];
__device__ __half g_act[NN_MAX * HID];
__device__ int    g_base[1];
__device__ unsigned short g_Whi1[HID * HID];
__device__ unsigned short g_Wlo1[HID * HID];
__device__ unsigned short g_Whi2[HID * HID];
__device__ unsigned short g_Wlo2[HID * HID];

static cudaStream_t g_s2 = nullptr;
static cudaEvent_t  g_ev0 = nullptr, g_ev1 = nullptr;
namespace {
struct SideInit {
    SideInit() {
        cudaStreamCreateWithFlags(&g_s2, cudaStreamNonBlocking);
        cudaEventCreateWithFlags(&g_ev0, cudaEventDisableTiming);
        cudaEventCreateWithFlags(&g_ev1, cudaEventDisableTiming);
    }
};
SideInit g_side_init;
}

// ---------------- setup ----------------
__global__ void k_setup(const float* __restrict__ Wa, unsigned short* hia, unsigned short* loa,
                        const float* __restrict__ Wb, unsigned short* hib, unsigned short* lob,
                        int* deg, int* base, int n) {
    int t = blockIdx.x * 256 + threadIdx.x;
    if (t < HID * HID) {
        float w = Wa[t];
        __nv_bfloat16 h = __float2bfloat16(w);
        float r = w - __bfloat162float(h);
        hia[t] = __bfloat16_as_ushort(h);
        loa[t] = __bfloat16_as_ushort(__float2bfloat16(r));
    } else if (t < 2 * HID * HID) {
        int i = t - HID * HID;
        float w = Wb[i];
        __nv_bfloat16 h = __float2bfloat16(w);
        float r = w - __bfloat162float(h);
        hib[i] = __bfloat16_as_ushort(h);
        lob[i] = __bfloat16_as_ushort(__float2bfloat16(r));
    }
    if (t < n) deg[t] = 0;
    if (t == 0) *base = 0;
}

// ---------------- CSR build ----------------
__global__ void k_count4(const int* __restrict__ dst, int* deg, int E) {
    int e4 = blockIdx.x * blockDim.x + threadIdx.x;
    int base = e4 * 4;
    if (base + 3 < E) {
        int4 d = *(const int4*)(dst + base);
        atomicAdd(&deg[d.x], 1);
        atomicAdd(&deg[d.y], 1);
        atomicAdd(&deg[d.z], 1);
        atomicAdd(&deg[d.w], 1);
    } else {
        for (int e = base; e < E; ++e) atomicAdd(&deg[dst[e]], 1);
    }
}

// off[] is an ORDER-FREE partition (not monotonic); end = off[i] + deg[i].
__global__ void k_assign(const int* __restrict__ deg, int* off, int* cursor,
                         float* dinv, int* base, int n) {
    __shared__ int s[256];
    __shared__ int blk_base;
    int tid = threadIdx.x;
    int gid = blockIdx.x * 256 + tid;
    int v = (gid < n) ? deg[gid] : 0;
    s[tid] = v;
    __syncthreads();
    #pragma unroll
    for (int d = 1; d < 256; d <<= 1) {
        int t = (tid >= d) ? s[tid - d] : 0;
        __syncthreads();
        s[tid] += t;
        __syncthreads();
    }
    if (tid == 255) blk_base = atomicAdd(base, s[255]);
    __syncthreads();
    if (gid < n) {
        int o = blk_base + s[tid] - v;
        off[gid] = o;
        cursor[gid] = o;
        dinv[gid] = rsqrtf((float)(v + 1));
    }
}

__global__ void k_fill_adj(const int* __restrict__ src, const int* __restrict__ dst,
                           int* cursor, int* adj, int E) {
    int e = blockIdx.x * blockDim.x + threadIdx.x;
    if (e < E) {
        int d = dst[e];
        int pos = atomicAdd(&cursor[d], 1);
        adj[pos] = src[e];
    }
}

// ---------------- HMMA GEMM ----------------
#define LDA 136
#define TILE_B (128 * LDA * 2)
#define GEMM_SMEM (4 * TILE_B)

__device__ __forceinline__ uint32_t smem_u32(const void* p) {
    uint32_t a;
    asm("{ .reg .u64 t; cvta.to.shared.u64 t, %1; cvt.u32.u64 %0, t; }" : "=r"(a) : "l"(p));
    return a;
}
__device__ __forceinline__ void ldsm_x4(uint32_t* r, uint32_t addr) {
    asm volatile("ldmatrix.sync.aligned.m8n8.x4.shared.b16 {%0,%1,%2,%3}, [%4];"
                 : "=r"(r[0]), "=r"(r[1]), "=r"(r[2]), "=r"(r[3]) : "r"(addr));
}
__device__ __forceinline__ void ldsm_x4t(uint32_t* r, uint32_t addr) {
    asm volatile("ldmatrix.sync.aligned.m8n8.x4.trans.shared.b16 {%0,%1,%2,%3}, [%4];"
                 : "=r"(r[0]), "=r"(r[1]), "=r"(r[2]), "=r"(r[3]) : "r"(addr));
}
__device__ __forceinline__ void mma_bf16(float* c, const uint32_t* a, const uint32_t* b) {
    asm volatile("mma.sync.aligned.m16n8k16.row.col.f32.bf16.bf16.f32 "
                 "{%0,%1,%2,%3}, {%4,%5,%6,%7}, {%8,%9}, {%0,%1,%2,%3};"
                 : "+f"(c[0]), "+f"(c[1]), "+f"(c[2]), "+f"(c[3])
                 : "r"(a[0]), "r"(a[1]), "r"(a[2]), "r"(a[3]), "r"(b[0]), "r"(b[1]));
}

__device__ __forceinline__ void load8(const float* X, int row, int g, float* f) {
    const float4* Xg = (const float4*)X;
    float4 v0 = __ldg(&Xg[row * 32 + g * 2]);
    float4 v1 = __ldg(&Xg[row * 32 + g * 2 + 1]);
    f[0] = v0.x; f[1] = v0.y; f[2] = v0.z; f[3] = v0.w;
    f[4] = v1.x; f[5] = v1.y; f[6] = v1.z; f[7] = v1.w;
}
__device__ __forceinline__ void load8(const __half* X, int row, int g, float* f) {
    const uint4* Xg = (const uint4*)X;
    uint4 v = __ldg(&Xg[row * 16 + g]);
    float2 p0 = __half22float2(*(__half2*)&v.x);
    float2 p1 = __half22float2(*(__half2*)&v.y);
    float2 p2 = __half22float2(*(__half2*)&v.z);
    float2 p3 = __half22float2(*(__half2*)&v.w);
    f[0] = p0.x; f[1] = p0.y; f[2] = p1.x; f[3] = p1.y;
    f[4] = p2.x; f[5] = p2.y; f[6] = p3.x; f[7] = p3.y;
}

template <typename T>
__global__ __launch_bounds__(256, 1)
void k_gemm_mma(const T* __restrict__ X,
                const unsigned short* __restrict__ Whi,
                const unsigned short* __restrict__ Wlo,
                const float* __restrict__ dinv,
                __half* __restrict__ out, int n)
{
    extern __shared__ char sm[];
    char* pAhi = sm;
    char* pAlo = sm + TILE_B;
    char* pBhi = sm + 2 * TILE_B;
    char* pBlo = sm + 3 * TILE_B;
    uint32_t uAhi = smem_u32(pAhi), uAlo = smem_u32(pAlo);
    uint32_t uBhi = smem_u32(pBhi), uBlo = smem_u32(pBlo);

    int tid = threadIdx.x, wid = tid >> 5, lid = tid & 31;
    int row0 = blockIdx.x * 128;

    {
        const uint4* sh = (const uint4*)Whi;
        const uint4* sl = (const uint4*)Wlo;
        uint4* dh = (uint4*)pBhi;
        uint4* dl = (uint4*)pBlo;
        #pragma unroll
        for (int i = 0; i < 8; ++i) {
            int idx = i * 256 + tid;
            int k = idx >> 4, g = idx & 15;
            dh[k * 17 + g] = sh[idx];
            dl[k * 17 + g] = sl[idx];
        }
    }

    {
        #pragma unroll
        for (int i = 0; i < 8; ++i) {
            int idx = i * 256 + tid;
            int r = idx >> 4, g = idx & 15;
            int grow = row0 + r;
            float f[8] = {0.f, 0.f, 0.f, 0.f, 0.f, 0.f, 0.f, 0.f};
            if (grow < n) load8(X, grow, g, f);
            uint32_t ph[4], pl[4];
            #pragma unroll
            for (int q = 0; q < 4; ++q) {
                __nv_bfloat16 h0 = __float2bfloat16(f[q * 2]);
                __nv_bfloat16 h1 = __float2bfloat16(f[q * 2 + 1]);
                float r0 = f[q * 2]     - __bfloat162float(h0);
                float r1 = f[q * 2 + 1] - __bfloat162float(h1);
                __nv_bfloat16 l0 = __float2bfloat16(r0);
                __nv_bfloat16 l1 = __float2bfloat16(r1);
                ph[q] = ((uint32_t)__bfloat16_as_ushort(h1) << 16) | __bfloat16_as_ushort(h0);
                pl[q] = ((uint32_t)__bfloat16_as_ushort(l1) << 16) | __bfloat16_as_ushort(l0);
            }
            uint4* dh = (uint4*)pAhi;
            uint4* dl = (uint4*)pAlo;
            dh[r * 17 + g] = make_uint4(ph[0], ph[1], ph[2], ph[3]);
            dl[r * 17 + g] = make_uint4(pl[0], pl[1], pl[2], pl[3]);
        }
    }
    __syncthreads();

    int m0 = wid * 16;
    float c[16][4];
    #pragma unroll
    for (int t = 0; t < 16; ++t)
        #pragma unroll
        for (int q = 0; q < 4; ++q) c[t][q] = 0.f;

    int a_row = m0 + (lid & 15);
    int a_k8  = (lid >> 4) * 8;
    int b_row = (lid & 15);
    int b_c8  = (lid >> 4) * 8;

    #pragma unroll
    for (int ks = 0; ks < 8; ++ks) {
        int kb = ks * 16;
        uint32_t ahi[4], alo[4];
        uint32_t a_off = ((uint32_t)(a_row * LDA + kb + a_k8)) * 2u;
        ldsm_x4(ahi, uAhi + a_off);
        ldsm_x4(alo, uAlo + a_off);

        uint32_t b_base = ((uint32_t)((kb + b_row) * LDA)) * 2u;
        #pragma unroll
        for (int ntp = 0; ntp < 8; ++ntp) {
            uint32_t bhi[4], blo[4];
            uint32_t b_off = b_base + (uint32_t)(ntp * 16 + b_c8) * 2u;
            ldsm_x4t(bhi, uBhi + b_off);
            ldsm_x4t(blo, uBlo + b_off);
            mma_bf16(c[ntp * 2],     ahi, bhi);
            mma_bf16(c[ntp * 2],     ahi, blo);
            mma_bf16(c[ntp * 2],     alo, bhi);
            mma_bf16(c[ntp * 2 + 1], ahi, bhi + 2);
            mma_bf16(c[ntp * 2 + 1], ahi, blo + 2);
            mma_bf16(c[ntp * 2 + 1], alo, bhi + 2);
        }
    }

    {
        int ml = lid >> 2;
        int n0 = (lid & 3) * 2;
        int r0g = row0 + m0 + ml;
        int r1g = r0g + 8;
        float s0 = (r0g < n) ? dinv[r0g] : 0.f;
        float s1 = (r1g < n) ? dinv[r1g] : 0.f;
        #pragma unroll
        for (int nt = 0; nt < 16; ++nt) {
            int col = nt * 8 + n0;
            if (r0g < n) {
                __half2 h = __floats2half2_rn(c[nt][0] * s0, c[nt][1] * s0);
                *(__half2*)(out + (size_t)r0g * HID + col) = h;
            }
            if (r1g < n) {
                __half2 h = __floats2half2_rn(c[nt][2] * s1, c[nt][3] * s1);
                *(__half2*)(out + (size_t)r1g * HID + col) = h;
            }
        }
    }
}

// ---------------- Aggregation + bias + LayerNorm + ReLU ----------------
// HALF-WARP-PER-NODE: 256 threads = 16 nodes/block. Half-warp lane hl covers
// cols hl*8..hl*8+7 via one uint4 (16B = 8 halves) per neighbor row.
// One LDG.128 instruction services both halves' rows. LN reduce = 16-lane shfl.

__device__ __forceinline__ void acc8(uint4 v, float* a) {
    float2 p0 = __half22float2(*(__half2*)&v.x);
    float2 p1 = __half22float2(*(__half2*)&v.y);
    float2 p2 = __half22float2(*(__half2*)&v.z);
    float2 p3 = __half22float2(*(__half2*)&v.w);
    a[0] += p0.x; a[1] += p0.y; a[2] += p1.x; a[3] += p1.y;
    a[4] += p2.x; a[5] += p2.y; a[6] += p3.x; a[7] += p3.y;
}

__device__ __forceinline__ float hw_sum(float v) {
    #pragma unroll
    for (int o = 8; o; o >>= 1) v += __shfl_xor_sync(0xffffffffu, v, o);
    return v;
}

__device__ __forceinline__ void store8(float* out, int i, int hl, const float* v) {
    float4* o4 = (float4*)out;
    o4[(size_t)i * 32 + hl * 2]     = make_float4(v[0], v[1], v[2], v[3]);
    o4[(size_t)i * 32 + hl * 2 + 1] = make_float4(v[4], v[5], v[6], v[7]);
}
__device__ __forceinline__ void store8(__half* out, int i, int hl, const float* v) {
    __half2 h0 = __floats2half2_rn(v[0], v[1]);
    __half2 h1 = __floats2half2_rn(v[2], v[3]);
    __half2 h2 = __floats2half2_rn(v[4], v[5]);
    __half2 h3 = __floats2half2_rn(v[6], v[7]);
    uint4 u;
    u.x = *(uint32_t*)&h0; u.y = *(uint32_t*)&h1;
    u.z = *(uint32_t*)&h2; u.w = *(uint32_t*)&h3;
    ((uint4*)out)[(size_t)i * 16 + hl] = u;
}

template <typename OutT>
__global__ __launch_bounds__(256)
void k_agg_ln(const uint4* __restrict__ ht16, const int* __restrict__ adj,
              const int* __restrict__ off, const int* __restrict__ deg,
              const float* __restrict__ dinv,
              const float* __restrict__ bias, const float* __restrict__ gamma,
              const float* __restrict__ beta, OutT* __restrict__ out, int n) {
    int wid = threadIdx.x >> 5;
    int lane = threadIdx.x & 31;
    int half = lane >> 4;
    int hl = lane & 15;
    int i = blockIdx.x * 16 + wid * 2 + half;
    bool valid = (i < n);
    int iw = valid ? i : (n - 1);

    float a[8] = {0.f, 0.f, 0.f, 0.f, 0.f, 0.f, 0.f, 0.f};
    acc8(__ldg(&ht16[(size_t)iw * 16 + hl]), a);   // self row

    int s = __ldg(&off[iw]);
    int d = __ldg(&deg[iw]);
    int dother = __shfl_xor_sync(0xffffffffu, d, 16);
    int dmax = d > dother ? d : dother;

    for (int t = 0; t < dmax; t += 4) {
        #pragma unroll
        for (int k = 0; k < 4; ++k) {
            if (t + k < d) {
                int j = __ldg(&adj[s + t + k]);
                acc8(__ldg(&ht16[(size_t)j * 16 + hl]), a);
            }
        }
    }

    float di = __ldg(&dinv[iw]);
    float4 bb0 = ((const float4*)bias)[hl * 2];
    float4 bb1 = ((const float4*)bias)[hl * 2 + 1];
    float v[8];
    v[0] = a[0] * di + bb0.x; v[1] = a[1] * di + bb0.y;
    v[2] = a[2] * di + bb0.z; v[3] = a[3] * di + bb0.w;
    v[4] = a[4] * di + bb1.x; v[5] = a[5] * di + bb1.y;
    v[6] = a[6] * di + bb1.z; v[7] = a[7] * di + bb1.w;

    float tot = ((v[0] + v[1]) + (v[2] + v[3])) + ((v[4] + v[5]) + (v[6] + v[7]));
    float mu = hw_sum(tot) * (1.0f / 128.0f);
    float dv[8], sq = 0.f;
    #pragma unroll
    for (int q = 0; q < 8; ++q) { dv[q] = v[q] - mu; sq += dv[q] * dv[q]; }
    float var = hw_sum(sq) * (1.0f / 128.0f);
    float rs = rsqrtf(var + 1e-5f);

    float4 gg0 = ((const float4*)gamma)[hl * 2];
    float4 gg1 = ((const float4*)gamma)[hl * 2 + 1];
    float4 be0 = ((const float4*)beta)[hl * 2];
    float4 be1 = ((const float4*)beta)[hl * 2 + 1];
    float o[8];
    o[0] = fmaxf(dv[0] * rs * gg0.x + be0.x, 0.0f);
    o[1] = fmaxf(dv[1] * rs * gg0.y + be0.y, 0.0f);
    o[2] = fmaxf(dv[2] * rs * gg0.z + be0.z, 0.0f);
    o[3] = fmaxf(dv[3] * rs * gg0.w + be0.w, 0.0f);
    o[4] = fmaxf(dv[4] * rs * gg1.x + be1.x, 0.0f);
    o[5] = fmaxf(dv[5] * rs * gg1.y + be1.y, 0.0f);
    o[6] = fmaxf(dv[6] * rs * gg1.z + be1.z, 0.0f);
    o[7] = fmaxf(dv[7] * rs * gg1.w + be1.w, 0.0f);

    if (valid) store8(out, i, hl, o);
}

// ---------------- launch ----------------
extern "C" void kernel_launch(void* const* d_in, const int* in_sizes, int n_in,
                              void* d_out, int out_size) {
    const float* x     = (const float*)d_in[0];
    const int*   edges = (const int*)d_in[1];
    const float* W1    = (const float*)d_in[2];
    const float* b1    = (const float*)d_in[3];
    const float* g1    = (const float*)d_in[4];
    const float* be1   = (const float*)d_in[5];
    const float* W2    = (const float*)d_in[6];
    const float* b2    = (const float*)d_in[7];
    const float* g2    = (const float*)d_in[8];
    const float* be2   = (const float*)d_in[9];
    float* out = (float*)d_out;

    int n = in_sizes[0] / HID;
    int E = in_sizes[1] / 2;
    const int* src = edges;
    const int* dst = edges + E;

    int *deg, *off, *cursor, *adj, *base;
    float *dinv;
    __half *ht, *act;
    unsigned short *whi1, *wlo1, *whi2, *wlo2;
    cudaGetSymbolAddress((void**)&deg, g_deg);
    cudaGetSymbolAddress((void**)&off, g_off);
    cudaGetSymbolAddress((void**)&cursor, g_cursor);
    cudaGetSymbolAddress((void**)&adj, g_adj);
    cudaGetSymbolAddress((void**)&base, g_base);
    cudaGetSymbolAddress((void**)&dinv, g_dinv);
    cudaGetSymbolAddress((void**)&ht, g_ht);
    cudaGetSymbolAddress((void**)&act, g_act);
    cudaGetSymbolAddress((void**)&whi1, g_Whi1);
    cudaGetSymbolAddress((void**)&wlo1, g_Wlo1);
    cudaGetSymbolAddress((void**)&whi2, g_Whi2);
    cudaGetSymbolAddress((void**)&wlo2, g_Wlo2);

    static bool attr_done = false;
    if (!attr_done) {
        cudaFuncSetAttribute(k_gemm_mma<float>, cudaFuncAttributeMaxDynamicSharedMemorySize, GEMM_SMEM);
        cudaFuncSetAttribute(k_gemm_mma<__half>, cudaFuncAttributeMaxDynamicSharedMemorySize, GEMM_SMEM);
        attr_done = true;
    }

    int nbN  = (n + 255) / 256;
    int nbE  = (E + 255) / 256;
    int nbE4 = ((E + 3) / 4 + 255) / 256;
    int nbG  = (n + 127) / 128;
    int nbA  = (n + 15) / 16;

    k_setup<<<256, 256>>>(W1, whi1, wlo1, W2, whi2, wlo2, deg, base, n);
    k_count4<<<nbE4, 256>>>(dst, deg, E);
    k_assign<<<nbN, 256>>>(deg, off, cursor, dinv, base, n);

    bool fork = (g_s2 && g_ev0 && g_ev1);
    if (fork) {
        cudaEventRecord(g_ev0, 0);
        cudaStreamWaitEvent(g_s2, g_ev0, 0);
        k_fill_adj<<<nbE, 256, 0, g_s2>>>(src, dst, cursor, adj, E);
        k_gemm_mma<float><<<nbG, 256, GEMM_SMEM>>>(x, whi1, wlo1, dinv, ht, n);
        cudaEventRecord(g_ev1, g_s2);
        cudaStreamWaitEvent((cudaStream_t)0, g_ev1, 0);
    } else {
        k_fill_adj<<<nbE, 256>>>(src, dst, cursor, adj, E);
        k_gemm_mma<float><<<nbG, 256, GEMM_SMEM>>>(x, whi1, wlo1, dinv, ht, n);
    }

    k_agg_ln<__half><<<nbA, 256>>>((const uint4*)ht, adj, off, deg, dinv, b1, g1, be1, act, n);
    k_gemm_mma<__half><<<nbG, 256, GEMM_SMEM>>>(act, whi2, wlo2, dinv, ht, n);
    k_agg_ln<float><<<nbA, 256>>>((const uint4*)ht, adj, off, deg, dinv, b2, g2, be2, out, n);
}

// round 16
// speedup vs baseline: 1.0523x; 1.0523x over previous
#include <cuda_runtime.h>
#include <cuda_bf16.h>
#include <cuda_fp16.h>
#include <cstdint>

#define NN_MAX 50000
#define NE_MAX 800000
#define HID 128

// ---------------- scratch (device globals) ----------------
__device__ int    g_deg[NN_MAX];
__device__ int    g_off[NN_MAX + 1];
__device__ int    g_cursor[NN_MAX];
__device__ int    g_adj[NE_MAX];
__device__ float  g_dinv[NN_MAX];
__device__ __half g_ht[NN_MAX * HID];
__device__ __half g_act[NN_MAX * HID];
__device__ int    g_base[1];
__device__ unsigned short g_Whi1[HID * HID];
__device__ unsigned short g_Wlo1[HID * HID];
__device__ unsigned short g_Whi2[HID * HID];
__device__ unsigned short g_Wlo2[HID * HID];

static cudaStream_t g_s2 = nullptr;
static cudaEvent_t  g_ev0 = nullptr, g_evW = nullptr, g_evA = nullptr, g_evF = nullptr;
namespace {
struct SideInit {
    SideInit() {
        cudaStreamCreateWithFlags(&g_s2, cudaStreamNonBlocking);
        cudaEventCreateWithFlags(&g_ev0, cudaEventDisableTiming);
        cudaEventCreateWithFlags(&g_evW, cudaEventDisableTiming);
        cudaEventCreateWithFlags(&g_evA, cudaEventDisableTiming);
        cudaEventCreateWithFlags(&g_evF, cudaEventDisableTiming);
    }
};
SideInit g_side_init;
}

// ---------------- W prep (both layers, one launch) ----------------
__global__ void k_prepW2(const float* __restrict__ Wa, unsigned short* hia, unsigned short* loa,
                         const float* __restrict__ Wb, unsigned short* hib, unsigned short* lob) {
    int e = blockIdx.x * 256 + threadIdx.x;
    const float* W = (e < HID * HID) ? Wa : Wb;
    unsigned short* hi = (e < HID * HID) ? hia : hib;
    unsigned short* lo = (e < HID * HID) ? loa : lob;
    int idx = (e < HID * HID) ? e : e - HID * HID;
    float w = W[idx];
    __nv_bfloat16 h = __float2bfloat16(w);
    float r = w - __bfloat162float(h);
    hi[idx] = __bfloat16_as_ushort(h);
    lo[idx] = __bfloat16_as_ushort(__float2bfloat16(r));
}

// ---------------- CSR build ----------------
__global__ void k_count4(const int* __restrict__ dst, int* deg, int E) {
    int e4 = blockIdx.x * blockDim.x + threadIdx.x;
    int base = e4 * 4;
    if (base + 3 < E) {
        int4 d = *(const int4*)(dst + base);
        atomicAdd(&deg[d.x], 1);
        atomicAdd(&deg[d.y], 1);
        atomicAdd(&deg[d.z], 1);
        atomicAdd(&deg[d.w], 1);
    } else {
        for (int e = base; e < E; ++e) atomicAdd(&deg[dst[e]], 1);
    }
}

// off[] is an ORDER-FREE partition (not monotonic); end = off[i] + deg[i].
__global__ void k_assign(const int* __restrict__ deg, int* off, int* cursor,
                         float* dinv, int* base, int n) {
    __shared__ int s[256];
    __shared__ int blk_base;
    int tid = threadIdx.x;
    int gid = blockIdx.x * 256 + tid;
    int v = (gid < n) ? deg[gid] : 0;
    s[tid] = v;
    __syncthreads();
    #pragma unroll
    for (int d = 1; d < 256; d <<= 1) {
        int t = (tid >= d) ? s[tid - d] : 0;
        __syncthreads();
        s[tid] += t;
        __syncthreads();
    }
    if (tid == 255) blk_base = atomicAdd(base, s[255]);
    __syncthreads();
    if (gid < n) {
        int o = blk_base + s[tid] - v;
        off[gid] = o;
        cursor[gid] = o;
        dinv[gid] = rsqrtf((float)(v + 1));
    }
}

__global__ void k_fill_adj(const int* __restrict__ src, const int* __restrict__ dst,
                           int* cursor, int* adj, int E) {
    int e = blockIdx.x * blockDim.x + threadIdx.x;
    if (e < E) {
        int d = dst[e];
        int pos = atomicAdd(&cursor[d], 1);
        adj[pos] = src[e];
    }
}

// ---------------- HMMA GEMM ----------------
#define LDA 136
#define TILE_B (128 * LDA * 2)
#define GEMM_SMEM (4 * TILE_B)

__device__ __forceinline__ uint32_t smem_u32(const void* p) {
    uint32_t a;
    asm("{ .reg .u64 t; cvta.to.shared.u64 t, %1; cvt.u32.u64 %0, t; }" : "=r"(a) : "l"(p));
    return a;
}
__device__ __forceinline__ void ldsm_x4(uint32_t* r, uint32_t addr) {
    asm volatile("ldmatrix.sync.aligned.m8n8.x4.shared.b16 {%0,%1,%2,%3}, [%4];"
                 : "=r"(r[0]), "=r"(r[1]), "=r"(r[2]), "=r"(r[3]) : "r"(addr));
}
__device__ __forceinline__ void ldsm_x4t(uint32_t* r, uint32_t addr) {
    asm volatile("ldmatrix.sync.aligned.m8n8.x4.trans.shared.b16 {%0,%1,%2,%3}, [%4];"
                 : "=r"(r[0]), "=r"(r[1]), "=r"(r[2]), "=r"(r[3]) : "r"(addr));
}
__device__ __forceinline__ void mma_bf16(float* c, const uint32_t* a, const uint32_t* b) {
    asm volatile("mma.sync.aligned.m16n8k16.row.col.f32.bf16.bf16.f32 "
                 "{%0,%1,%2,%3}, {%4,%5,%6,%7}, {%8,%9}, {%0,%1,%2,%3};"
                 : "+f"(c[0]), "+f"(c[1]), "+f"(c[2]), "+f"(c[3])
                 : "r"(a[0]), "r"(a[1]), "r"(a[2]), "r"(a[3]), "r"(b[0]), "r"(b[1]));
}

__device__ __forceinline__ void load8(const float* X, int row, int g, float* f) {
    const float4* Xg = (const float4*)X;
    float4 v0 = __ldg(&Xg[row * 32 + g * 2]);
    float4 v1 = __ldg(&Xg[row * 32 + g * 2 + 1]);
    f[0] = v0.x; f[1] = v0.y; f[2] = v0.z; f[3] = v0.w;
    f[4] = v1.x; f[5] = v1.y; f[6] = v1.z; f[7] = v1.w;
}
__device__ __forceinline__ void load8(const __half* X, int row, int g, float* f) {
    const uint4* Xg = (const uint4*)X;
    uint4 v = __ldg(&Xg[row * 16 + g]);
    float2 p0 = __half22float2(*(__half2*)&v.x);
    float2 p1 = __half22float2(*(__half2*)&v.y);
    float2 p2 = __half22float2(*(__half2*)&v.z);
    float2 p3 = __half22float2(*(__half2*)&v.w);
    f[0] = p0.x; f[1] = p0.y; f[2] = p1.x; f[3] = p1.y;
    f[4] = p2.x; f[5] = p2.y; f[6] = p3.x; f[7] = p3.y;
}

template <typename T>
__global__ __launch_bounds__(256, 1)
void k_gemm_mma(const T* __restrict__ X,
                const unsigned short* __restrict__ Whi,
                const unsigned short* __restrict__ Wlo,
                const float* __restrict__ dinv,
                __half* __restrict__ out, int n)
{
    extern __shared__ char sm[];
    char* pAhi = sm;
    char* pAlo = sm + TILE_B;
    char* pBhi = sm + 2 * TILE_B;
    char* pBlo = sm + 3 * TILE_B;
    uint32_t uAhi = smem_u32(pAhi), uAlo = smem_u32(pAlo);
    uint32_t uBhi = smem_u32(pBhi), uBlo = smem_u32(pBlo);

    int tid = threadIdx.x, wid = tid >> 5, lid = tid & 31;
    int row0 = blockIdx.x * 128;

    {
        const uint4* sh = (const uint4*)Whi;
        const uint4* sl = (const uint4*)Wlo;
        uint4* dh = (uint4*)pBhi;
        uint4* dl = (uint4*)pBlo;
        #pragma unroll
        for (int i = 0; i < 8; ++i) {
            int idx = i * 256 + tid;
            int k = idx >> 4, g = idx & 15;
            dh[k * 17 + g] = sh[idx];
            dl[k * 17 + g] = sl[idx];
        }
    }

    {
        #pragma unroll
        for (int i = 0; i < 8; ++i) {
            int idx = i * 256 + tid;
            int r = idx >> 4, g = idx & 15;
            int grow = row0 + r;
            float f[8] = {0.f, 0.f, 0.f, 0.f, 0.f, 0.f, 0.f, 0.f};
            if (grow < n) load8(X, grow, g, f);
            uint32_t ph[4], pl[4];
            #pragma unroll
            for (int q = 0; q < 4; ++q) {
                __nv_bfloat16 h0 = __float2bfloat16(f[q * 2]);
                __nv_bfloat16 h1 = __float2bfloat16(f[q * 2 + 1]);
                float r0 = f[q * 2]     - __bfloat162float(h0);
                float r1 = f[q * 2 + 1] - __bfloat162float(h1);
                __nv_bfloat16 l0 = __float2bfloat16(r0);
                __nv_bfloat16 l1 = __float2bfloat16(r1);
                ph[q] = ((uint32_t)__bfloat16_as_ushort(h1) << 16) | __bfloat16_as_ushort(h0);
                pl[q] = ((uint32_t)__bfloat16_as_ushort(l1) << 16) | __bfloat16_as_ushort(l0);
            }
            uint4* dh = (uint4*)pAhi;
            uint4* dl = (uint4*)pAlo;
            dh[r * 17 + g] = make_uint4(ph[0], ph[1], ph[2], ph[3]);
            dl[r * 17 + g] = make_uint4(pl[0], pl[1], pl[2], pl[3]);
        }
    }
    __syncthreads();

    int m0 = wid * 16;
    float c[16][4];
    #pragma unroll
    for (int t = 0; t < 16; ++t)
        #pragma unroll
        for (int q = 0; q < 4; ++q) c[t][q] = 0.f;

    int a_row = m0 + (lid & 15);
    int a_k8  = (lid >> 4) * 8;
    int b_row = (lid & 15);
    int b_c8  = (lid >> 4) * 8;

    #pragma unroll
    for (int ks = 0; ks < 8; ++ks) {
        int kb = ks * 16;
        uint32_t ahi[4], alo[4];
        uint32_t a_off = ((uint32_t)(a_row * LDA + kb + a_k8)) * 2u;
        ldsm_x4(ahi, uAhi + a_off);
        ldsm_x4(alo, uAlo + a_off);

        uint32_t b_base = ((uint32_t)((kb + b_row) * LDA)) * 2u;
        #pragma unroll
        for (int ntp = 0; ntp < 8; ++ntp) {
            uint32_t bhi[4], blo[4];
            uint32_t b_off = b_base + (uint32_t)(ntp * 16 + b_c8) * 2u;
            ldsm_x4t(bhi, uBhi + b_off);
            ldsm_x4t(blo, uBlo + b_off);
            mma_bf16(c[ntp * 2],     ahi, bhi);
            mma_bf16(c[ntp * 2],     ahi, blo);
            mma_bf16(c[ntp * 2],     alo, bhi);
            mma_bf16(c[ntp * 2 + 1], ahi, bhi + 2);
            mma_bf16(c[ntp * 2 + 1], ahi, blo + 2);
            mma_bf16(c[ntp * 2 + 1], alo, bhi + 2);
        }
    }

    {
        int ml = lid >> 2;
        int n0 = (lid & 3) * 2;
        int r0g = row0 + m0 + ml;
        int r1g = r0g + 8;
        float s0 = (r0g < n) ? dinv[r0g] : 0.f;
        float s1 = (r1g < n) ? dinv[r1g] : 0.f;
        #pragma unroll
        for (int nt = 0; nt < 16; ++nt) {
            int col = nt * 8 + n0;
            if (r0g < n) {
                __half2 h = __floats2half2_rn(c[nt][0] * s0, c[nt][1] * s0);
                *(__half2*)(out + (size_t)r0g * HID + col) = h;
            }
            if (r1g < n) {
                __half2 h = __floats2half2_rn(c[nt][2] * s1, c[nt][3] * s1);
                *(__half2*)(out + (size_t)r1g * HID + col) = h;
            }
        }
    }
}

// ---------------- Aggregation + bias + LayerNorm + ReLU (R14-proven) ----------------
// WARP-PER-NODE: 256 threads = 8 nodes/block. Lane l covers cols 4l..4l+3
// via one uint2 (8B) load per neighbor row. LN reduce = intra-warp shfl only.

__device__ __forceinline__ float warp_sum(float v) {
    #pragma unroll
    for (int o = 16; o; o >>= 1) v += __shfl_xor_sync(0xffffffffu, v, o);
    return v;
}

__device__ __forceinline__ void acc_row(const uint2* __restrict__ ht4, int j, int lane,
                                        float2& aA, float2& aB) {
    uint2 v = __ldg(&ht4[(size_t)j * 32 + lane]);
    float2 p0 = __half22float2(*(__half2*)&v.x);
    float2 p1 = __half22float2(*(__half2*)&v.y);
    aA.x += p0.x; aA.y += p0.y;
    aB.x += p1.x; aB.y += p1.y;
}

__device__ __forceinline__ void store4(float* out, int i, int lane, float4 v) {
    ((float4*)out)[(size_t)i * 32 + lane] = v;
}
__device__ __forceinline__ void store4(__half* out, int i, int lane, float4 v) {
    __half2 h0 = __floats2half2_rn(v.x, v.y);
    __half2 h1 = __floats2half2_rn(v.z, v.w);
    uint2 u;
    u.x = *(uint32_t*)&h0;
    u.y = *(uint32_t*)&h1;
    ((uint2*)out)[(size_t)i * 32 + lane] = u;
}

template <typename OutT>
__global__ __launch_bounds__(256)
void k_agg_ln(const uint2* __restrict__ ht4, const int* __restrict__ adj,
              const int* __restrict__ off, const int* __restrict__ deg,
              const float* __restrict__ dinv,
              const float* __restrict__ bias, const float* __restrict__ gamma,
              const float* __restrict__ beta, OutT* __restrict__ out, int n) {
    int wid = threadIdx.x >> 5;
    int lane = threadIdx.x & 31;
    int i = blockIdx.x * 8 + wid;
    if (i >= n) return;

    float2 aA = make_float2(0.f, 0.f), aB = make_float2(0.f, 0.f);
    acc_row(ht4, i, lane, aA, aB);

    int s = __ldg(&off[i]);
    int e = s + __ldg(&deg[i]);
    int p = s;
    for (; p + 8 <= e; p += 8) {
        int j0 = __ldg(&adj[p]);
        int j1 = __ldg(&adj[p + 1]);
        int j2 = __ldg(&adj[p + 2]);
        int j3 = __ldg(&adj[p + 3]);
        int j4 = __ldg(&adj[p + 4]);
        int j5 = __ldg(&adj[p + 5]);
        int j6 = __ldg(&adj[p + 6]);
        int j7 = __ldg(&adj[p + 7]);
        acc_row(ht4, j0, lane, aA, aB);
        acc_row(ht4, j1, lane, aA, aB);
        acc_row(ht4, j2, lane, aA, aB);
        acc_row(ht4, j3, lane, aA, aB);
        acc_row(ht4, j4, lane, aA, aB);
        acc_row(ht4, j5, lane, aA, aB);
        acc_row(ht4, j6, lane, aA, aB);
        acc_row(ht4, j7, lane, aA, aB);
    }
    for (; p + 4 <= e; p += 4) {
        int j0 = __ldg(&adj[p]);
        int j1 = __ldg(&adj[p + 1]);
        int j2 = __ldg(&adj[p + 2]);
        int j3 = __ldg(&adj[p + 3]);
        acc_row(ht4, j0, lane, aA, aB);
        acc_row(ht4, j1, lane, aA, aB);
        acc_row(ht4, j2, lane, aA, aB);
        acc_row(ht4, j3, lane, aA, aB);
    }
    for (; p < e; ++p) acc_row(ht4, __ldg(&adj[p]), lane, aA, aB);

    float di = __ldg(&dinv[i]);
    float4 bb = ((const float4*)bias)[lane];
    float v0 = aA.x * di + bb.x;
    float v1 = aA.y * di + bb.y;
    float v2 = aB.x * di + bb.z;
    float v3 = aB.y * di + bb.w;

    float mu = warp_sum((v0 + v1) + (v2 + v3)) * (1.0f / 128.0f);
    float d0 = v0 - mu, d1 = v1 - mu, d2 = v2 - mu, d3 = v3 - mu;
    float var = warp_sum((d0 * d0 + d1 * d1) + (d2 * d2 + d3 * d3)) * (1.0f / 128.0f);
    float rs = rsqrtf(var + 1e-5f);
    float4 gg = ((const float4*)gamma)[lane];
    float4 be = ((const float4*)beta)[lane];
    float4 o = make_float4(fmaxf(d0 * rs * gg.x + be.x, 0.0f),
                           fmaxf(d1 * rs * gg.y + be.y, 0.0f),
                           fmaxf(d2 * rs * gg.z + be.z, 0.0f),
                           fmaxf(d3 * rs * gg.w + be.w, 0.0f));
    store4(out, i, lane, o);
}

// ---------------- launch ----------------
extern "C" void kernel_launch(void* const* d_in, const int* in_sizes, int n_in,
                              void* d_out, int out_size) {
    const float* x     = (const float*)d_in[0];
    const int*   edges = (const int*)d_in[1];
    const float* W1    = (const float*)d_in[2];
    const float* b1    = (const float*)d_in[3];
    const float* g1    = (const float*)d_in[4];
    const float* be1   = (const float*)d_in[5];
    const float* W2    = (const float*)d_in[6];
    const float* b2    = (const float*)d_in[7];
    const float* g2    = (const float*)d_in[8];
    const float* be2   = (const float*)d_in[9];
    float* out = (float*)d_out;

    int n = in_sizes[0] / HID;
    int E = in_sizes[1] / 2;
    const int* src = edges;
    const int* dst = edges + E;

    int *deg, *off, *cursor, *adj, *base;
    float *dinv;
    __half *ht, *act;
    unsigned short *whi1, *wlo1, *whi2, *wlo2;
    cudaGetSymbolAddress((void**)&deg, g_deg);
    cudaGetSymbolAddress((void**)&off, g_off);
    cudaGetSymbolAddress((void**)&cursor, g_cursor);
    cudaGetSymbolAddress((void**)&adj, g_adj);
    cudaGetSymbolAddress((void**)&base, g_base);
    cudaGetSymbolAddress((void**)&dinv, g_dinv);
    cudaGetSymbolAddress((void**)&ht, g_ht);
    cudaGetSymbolAddress((void**)&act, g_act);
    cudaGetSymbolAddress((void**)&whi1, g_Whi1);
    cudaGetSymbolAddress((void**)&wlo1, g_Wlo1);
    cudaGetSymbolAddress((void**)&whi2, g_Whi2);
    cudaGetSymbolAddress((void**)&wlo2, g_Wlo2);

    static bool attr_done = false;
    if (!attr_done) {
        cudaFuncSetAttribute(k_gemm_mma<float>, cudaFuncAttributeMaxDynamicSharedMemorySize, GEMM_SMEM);
        cudaFuncSetAttribute(k_gemm_mma<__half>, cudaFuncAttributeMaxDynamicSharedMemorySize, GEMM_SMEM);
        attr_done = true;
    }

    int nbN  = (n + 255) / 256;
    int nbE  = (E + 255) / 256;
    int nbE4 = ((E + 3) / 4 + 255) / 256;
    int nbG  = (n + 127) / 128;
    int nbA  = (n + 7) / 8;

    bool fork = (g_s2 && g_ev0 && g_evW && g_evA && g_evF);

    if (fork) {
        // side: W prep from t=0 (independent)
        cudaEventRecord(g_ev0, 0);
        cudaStreamWaitEvent(g_s2, g_ev0, 0);
        k_prepW2<<<128, 256, 0, g_s2>>>(W1, whi1, wlo1, W2, whi2, wlo2);
        cudaEventRecord(g_evW, g_s2);

        // main: CSR counting chain
        cudaMemsetAsync(deg, 0, n * sizeof(int));
        cudaMemsetAsync(base, 0, sizeof(int));
        k_count4<<<nbE4, 256>>>(dst, deg, E);
        k_assign<<<nbN, 256>>>(deg, off, cursor, dinv, base, n);
        cudaEventRecord(g_evA, (cudaStream_t)0);

        // side: fill_adj after assign
        cudaStreamWaitEvent(g_s2, g_evA, 0);
        k_fill_adj<<<nbE, 256, 0, g_s2>>>(src, dst, cursor, adj, E);
        cudaEventRecord(g_evF, g_s2);

        // main: GEMM1 (needs W + dinv), concurrent with fill_adj
        cudaStreamWaitEvent((cudaStream_t)0, g_evW, 0);
        k_gemm_mma<float><<<nbG, 256, GEMM_SMEM>>>(x, whi1, wlo1, dinv, ht, n);

        // join before agg1
        cudaStreamWaitEvent((cudaStream_t)0, g_evF, 0);
    } else {
        k_prepW2<<<128, 256>>>(W1, whi1, wlo1, W2, whi2, wlo2);
        cudaMemsetAsync(deg, 0, n * sizeof(int));
        cudaMemsetAsync(base, 0, sizeof(int));
        k_count4<<<nbE4, 256>>>(dst, deg, E);
        k_assign<<<nbN, 256>>>(deg, off, cursor, dinv, base, n);
        k_fill_adj<<<nbE, 256>>>(src, dst, cursor, adj, E);
        k_gemm_mma<float><<<nbG, 256, GEMM_SMEM>>>(x, whi1, wlo1, dinv, ht, n);
    }

    k_agg_ln<__half><<<nbA, 256>>>((const uint2*)ht, adj, off, deg, dinv, b1, g1, be1, act, n);
    k_gemm_mma<__half><<<nbG, 256, GEMM_SMEM>>>(act, whi2, wlo2, dinv, ht, n);
    k_agg_ln<float><<<nbA, 256>>>((const uint2*)ht, adj, off, deg, dinv, b2, g2, be2, out, n);
}

// round 17
// speedup vs baseline: 1.0841x; 1.0302x over previous
#include <cuda_runtime.h>
#include <cuda_bf16.h>
#include <cuda_fp16.h>
#include <cstdint>

#define NN_MAX 50000
#define NE_MAX 800000
#define HID 128

// ---------------- scratch (device globals) ----------------
__device__ int    g_deg[NN_MAX];
__device__ int    g_off[NN_MAX + 1];
__device__ int    g_cursor[NN_MAX];
__device__ int    g_adj[NE_MAX];
__device__ float  g_dinv[NN_MAX];
__device__ __half g_ht[NN_MAX * HID];
__device__ __half g_act[NN_MAX * HID];
__device__ int    g_base[1];
__device__ unsigned short g_Whi1[HID * HID];
__device__ unsigned short g_Wlo1[HID * HID];
__device__ unsigned short g_Whi2[HID * HID];
__device__ unsigned short g_Wlo2[HID * HID];

static cudaStream_t g_s2 = nullptr;
static cudaEvent_t  g_ev0 = nullptr, g_ev1 = nullptr;
namespace {
struct SideInit {
    SideInit() {
        cudaStreamCreateWithFlags(&g_s2, cudaStreamNonBlocking);
        cudaEventCreateWithFlags(&g_ev0, cudaEventDisableTiming);
        cudaEventCreateWithFlags(&g_ev1, cudaEventDisableTiming);
    }
};
SideInit g_side_init;
}

// ---------------- setup: W prep (both layers) + deg/base zeroing (R14-proven) ----------------
__global__ void k_setup(const float* __restrict__ Wa, unsigned short* hia, unsigned short* loa,
                        const float* __restrict__ Wb, unsigned short* hib, unsigned short* lob,
                        int* deg, int* base, int n) {
    int t = blockIdx.x * 256 + threadIdx.x;
    if (t < HID * HID) {
        float w = Wa[t];
        __nv_bfloat16 h = __float2bfloat16(w);
        float r = w - __bfloat162float(h);
        hia[t] = __bfloat16_as_ushort(h);
        loa[t] = __bfloat16_as_ushort(__float2bfloat16(r));
    } else if (t < 2 * HID * HID) {
        int i = t - HID * HID;
        float w = Wb[i];
        __nv_bfloat16 h = __float2bfloat16(w);
        float r = w - __bfloat162float(h);
        hib[i] = __bfloat16_as_ushort(h);
        lob[i] = __bfloat16_as_ushort(__float2bfloat16(r));
    }
    if (t < n) deg[t] = 0;
    if (t == 0) *base = 0;
}

// ---------------- CSR build ----------------
__global__ void k_count4(const int* __restrict__ dst, int* deg, int E) {
    int e4 = blockIdx.x * blockDim.x + threadIdx.x;
    int base = e4 * 4;
    if (base + 3 < E) {
        int4 d = *(const int4*)(dst + base);
        atomicAdd(&deg[d.x], 1);
        atomicAdd(&deg[d.y], 1);
        atomicAdd(&deg[d.z], 1);
        atomicAdd(&deg[d.w], 1);
    } else {
        for (int e = base; e < E; ++e) atomicAdd(&deg[dst[e]], 1);
    }
}

// off[] is an ORDER-FREE partition (not monotonic); end = off[i] + deg[i].
__global__ void k_assign(const int* __restrict__ deg, int* off, int* cursor,
                         float* dinv, int* base, int n) {
    __shared__ int s[256];
    __shared__ int blk_base;
    int tid = threadIdx.x;
    int gid = blockIdx.x * 256 + tid;
    int v = (gid < n) ? deg[gid] : 0;
    s[tid] = v;
    __syncthreads();
    #pragma unroll
    for (int d = 1; d < 256; d <<= 1) {
        int t = (tid >= d) ? s[tid - d] : 0;
        __syncthreads();
        s[tid] += t;
        __syncthreads();
    }
    if (tid == 255) blk_base = atomicAdd(base, s[255]);
    __syncthreads();
    if (gid < n) {
        int o = blk_base + s[tid] - v;
        off[gid] = o;
        cursor[gid] = o;
        dinv[gid] = rsqrtf((float)(v + 1));
    }
}

__global__ void k_fill_adj(const int* __restrict__ src, const int* __restrict__ dst,
                           int* cursor, int* adj, int E) {
    int e = blockIdx.x * blockDim.x + threadIdx.x;
    if (e < E) {
        int d = dst[e];
        int pos = atomicAdd(&cursor[d], 1);
        adj[pos] = src[e];
    }
}

// ---------------- HMMA GEMM: M-tile 64, 2 CTAs/SM ----------------
#define LDA 136
#define TILE_A (64 * LDA * 2)        // 17408 B
#define TILE_W (128 * LDA * 2)       // 34816 B
#define GEMM_SMEM (2 * TILE_A + 2 * TILE_W)   // 104448 B

__device__ __forceinline__ uint32_t smem_u32(const void* p) {
    uint32_t a;
    asm("{ .reg .u64 t; cvta.to.shared.u64 t, %1; cvt.u32.u64 %0, t; }" : "=r"(a) : "l"(p));
    return a;
}
__device__ __forceinline__ void ldsm_x4(uint32_t* r, uint32_t addr) {
    asm volatile("ldmatrix.sync.aligned.m8n8.x4.shared.b16 {%0,%1,%2,%3}, [%4];"
                 : "=r"(r[0]), "=r"(r[1]), "=r"(r[2]), "=r"(r[3]) : "r"(addr));
}
__device__ __forceinline__ void ldsm_x4t(uint32_t* r, uint32_t addr) {
    asm volatile("ldmatrix.sync.aligned.m8n8.x4.trans.shared.b16 {%0,%1,%2,%3}, [%4];"
                 : "=r"(r[0]), "=r"(r[1]), "=r"(r[2]), "=r"(r[3]) : "r"(addr));
}
__device__ __forceinline__ void mma_bf16(float* c, const uint32_t* a, const uint32_t* b) {
    asm volatile("mma.sync.aligned.m16n8k16.row.col.f32.bf16.bf16.f32 "
                 "{%0,%1,%2,%3}, {%4,%5,%6,%7}, {%8,%9}, {%0,%1,%2,%3};"
                 : "+f"(c[0]), "+f"(c[1]), "+f"(c[2]), "+f"(c[3])
                 : "r"(a[0]), "r"(a[1]), "r"(a[2]), "r"(a[3]), "r"(b[0]), "r"(b[1]));
}

__device__ __forceinline__ void load8(const float* X, int row, int g, float* f) {
    const float4* Xg = (const float4*)X;
    float4 v0 = __ldg(&Xg[row * 32 + g * 2]);
    float4 v1 = __ldg(&Xg[row * 32 + g * 2 + 1]);
    f[0] = v0.x; f[1] = v0.y; f[2] = v0.z; f[3] = v0.w;
    f[4] = v1.x; f[5] = v1.y; f[6] = v1.z; f[7] = v1.w;
}
__device__ __forceinline__ void load8(const __half* X, int row, int g, float* f) {
    const uint4* Xg = (const uint4*)X;
    uint4 v = __ldg(&Xg[row * 16 + g]);
    float2 p0 = __half22float2(*(__half2*)&v.x);
    float2 p1 = __half22float2(*(__half2*)&v.y);
    float2 p2 = __half22float2(*(__half2*)&v.z);
    float2 p3 = __half22float2(*(__half2*)&v.w);
    f[0] = p0.x; f[1] = p0.y; f[2] = p1.x; f[3] = p1.y;
    f[4] = p2.x; f[5] = p2.y; f[6] = p3.x; f[7] = p3.y;
}

template <typename T>
__global__ __launch_bounds__(256, 2)
void k_gemm_mma(const T* __restrict__ X,
                const unsigned short* __restrict__ Whi,
                const unsigned short* __restrict__ Wlo,
                const float* __restrict__ dinv,
                __half* __restrict__ out, int n)
{
    extern __shared__ char sm[];
    char* pAhi = sm;
    char* pAlo = sm + TILE_A;
    char* pBhi = sm + 2 * TILE_A;
    char* pBlo = sm + 2 * TILE_A + TILE_W;
    uint32_t uAhi = smem_u32(pAhi), uAlo = smem_u32(pAlo);
    uint32_t uBhi = smem_u32(pBhi), uBlo = smem_u32(pBlo);

    int tid = threadIdx.x, wid = tid >> 5, lid = tid & 31;
    int row0 = blockIdx.x * 64;

    // copy W hi/lo into smem (padded rows): 2048 uint4 each
    {
        const uint4* sh = (const uint4*)Whi;
        const uint4* sl = (const uint4*)Wlo;
        uint4* dh = (uint4*)pBhi;
        uint4* dl = (uint4*)pBlo;
        #pragma unroll
        for (int i = 0; i < 8; ++i) {
            int idx = i * 256 + tid;
            int k = idx >> 4, g = idx & 15;
            dh[k * 17 + g] = sh[idx];
            dl[k * 17 + g] = sl[idx];
        }
    }

    // convert X tile (64 rows) -> bf16 hi/lo: 1024 groups of 8
    {
        #pragma unroll
        for (int i = 0; i < 4; ++i) {
            int idx = i * 256 + tid;
            int r = idx >> 4, g = idx & 15;
            int grow = row0 + r;
            float f[8] = {0.f, 0.f, 0.f, 0.f, 0.f, 0.f, 0.f, 0.f};
            if (grow < n) load8(X, grow, g, f);
            uint32_t ph[4], pl[4];
            #pragma unroll
            for (int q = 0; q < 4; ++q) {
                __nv_bfloat16 h0 = __float2bfloat16(f[q * 2]);
                __nv_bfloat16 h1 = __float2bfloat16(f[q * 2 + 1]);
                float r0 = f[q * 2]     - __bfloat162float(h0);
                float r1 = f[q * 2 + 1] - __bfloat162float(h1);
                __nv_bfloat16 l0 = __float2bfloat16(r0);
                __nv_bfloat16 l1 = __float2bfloat16(r1);
                ph[q] = ((uint32_t)__bfloat16_as_ushort(h1) << 16) | __bfloat16_as_ushort(h0);
                pl[q] = ((uint32_t)__bfloat16_as_ushort(l1) << 16) | __bfloat16_as_ushort(l0);
            }
            uint4* dh = (uint4*)pAhi;
            uint4* dl = (uint4*)pAlo;
            dh[r * 17 + g] = make_uint4(ph[0], ph[1], ph[2], ph[3]);
            dl[r * 17 + g] = make_uint4(pl[0], pl[1], pl[2], pl[3]);
        }
    }
    __syncthreads();

    // warp w: rows (w&3)*16..+16, cols (w>>2)*64..+64
    int m0 = (wid & 3) * 16;
    int cbase = (wid >> 2) * 64;
    float c[8][4];
    #pragma unroll
    for (int t = 0; t < 8; ++t)
        #pragma unroll
        for (int q = 0; q < 4; ++q) c[t][q] = 0.f;

    int a_row = m0 + (lid & 15);
    int a_k8  = (lid >> 4) * 8;
    int b_row = (lid & 15);
    int b_c8  = (lid >> 4) * 8;

    #pragma unroll
    for (int ks = 0; ks < 8; ++ks) {
        int kb = ks * 16;
        uint32_t ahi[4], alo[4];
        uint32_t a_off = ((uint32_t)(a_row * LDA + kb + a_k8)) * 2u;
        ldsm_x4(ahi, uAhi + a_off);
        ldsm_x4(alo, uAlo + a_off);

        uint32_t b_base = ((uint32_t)((kb + b_row) * LDA)) * 2u;
        #pragma unroll
        for (int ntp = 0; ntp < 4; ++ntp) {
            uint32_t bhi[4], blo[4];
            uint32_t b_off = b_base + (uint32_t)(cbase + ntp * 16 + b_c8) * 2u;
            ldsm_x4t(bhi, uBhi + b_off);
            ldsm_x4t(blo, uBlo + b_off);
            mma_bf16(c[ntp * 2],     ahi, bhi);
            mma_bf16(c[ntp * 2],     ahi, blo);
            mma_bf16(c[ntp * 2],     alo, bhi);
            mma_bf16(c[ntp * 2 + 1], ahi, bhi + 2);
            mma_bf16(c[ntp * 2 + 1], ahi, blo + 2);
            mma_bf16(c[ntp * 2 + 1], alo, bhi + 2);
        }
    }

    // epilogue: scale by dinv, store fp16
    {
        int ml = lid >> 2;
        int n0 = (lid & 3) * 2;
        int r0g = row0 + m0 + ml;
        int r1g = r0g + 8;
        float s0 = (r0g < n) ? dinv[r0g] : 0.f;
        float s1 = (r1g < n) ? dinv[r1g] : 0.f;
        #pragma unroll
        for (int nt = 0; nt < 8; ++nt) {
            int col = cbase + nt * 8 + n0;
            if (r0g < n) {
                __half2 h = __floats2half2_rn(c[nt][0] * s0, c[nt][1] * s0);
                *(__half2*)(out + (size_t)r0g * HID + col) = h;
            }
            if (r1g < n) {
                __half2 h = __floats2half2_rn(c[nt][2] * s1, c[nt][3] * s1);
                *(__half2*)(out + (size_t)r1g * HID + col) = h;
            }
        }
    }
}

// ---------------- Aggregation + bias + LayerNorm + ReLU (R14-proven) ----------------
__device__ __forceinline__ float warp_sum(float v) {
    #pragma unroll
    for (int o = 16; o; o >>= 1) v += __shfl_xor_sync(0xffffffffu, v, o);
    return v;
}

__device__ __forceinline__ void acc_row(const uint2* __restrict__ ht4, int j, int lane,
                                        float2& aA, float2& aB) {
    uint2 v = __ldg(&ht4[(size_t)j * 32 + lane]);
    float2 p0 = __half22float2(*(__half2*)&v.x);
    float2 p1 = __half22float2(*(__half2*)&v.y);
    aA.x += p0.x; aA.y += p0.y;
    aB.x += p1.x; aB.y += p1.y;
}

__device__ __forceinline__ void store4(float* out, int i, int lane, float4 v) {
    ((float4*)out)[(size_t)i * 32 + lane] = v;
}
__device__ __forceinline__ void store4(__half* out, int i, int lane, float4 v) {
    __half2 h0 = __floats2half2_rn(v.x, v.y);
    __half2 h1 = __floats2half2_rn(v.z, v.w);
    uint2 u;
    u.x = *(uint32_t*)&h0;
    u.y = *(uint32_t*)&h1;
    ((uint2*)out)[(size_t)i * 32 + lane] = u;
}

template <typename OutT>
__global__ __launch_bounds__(256)
void k_agg_ln(const uint2* __restrict__ ht4, const int* __restrict__ adj,
              const int* __restrict__ off, const int* __restrict__ deg,
              const float* __restrict__ dinv,
              const float* __restrict__ bias, const float* __restrict__ gamma,
              const float* __restrict__ beta, OutT* __restrict__ out, int n) {
    int wid = threadIdx.x >> 5;
    int lane = threadIdx.x & 31;
    int i = blockIdx.x * 8 + wid;
    if (i >= n) return;

    float2 aA = make_float2(0.f, 0.f), aB = make_float2(0.f, 0.f);
    acc_row(ht4, i, lane, aA, aB);

    int s = __ldg(&off[i]);
    int e = s + __ldg(&deg[i]);
    int p = s;
    for (; p + 8 <= e; p += 8) {
        int j0 = __ldg(&adj[p]);
        int j1 = __ldg(&adj[p + 1]);
        int j2 = __ldg(&adj[p + 2]);
        int j3 = __ldg(&adj[p + 3]);
        int j4 = __ldg(&adj[p + 4]);
        int j5 = __ldg(&adj[p + 5]);
        int j6 = __ldg(&adj[p + 6]);
        int j7 = __ldg(&adj[p + 7]);
        acc_row(ht4, j0, lane, aA, aB);
        acc_row(ht4, j1, lane, aA, aB);
        acc_row(ht4, j2, lane, aA, aB);
        acc_row(ht4, j3, lane, aA, aB);
        acc_row(ht4, j4, lane, aA, aB);
        acc_row(ht4, j5, lane, aA, aB);
        acc_row(ht4, j6, lane, aA, aB);
        acc_row(ht4, j7, lane, aA, aB);
    }
    for (; p + 4 <= e; p += 4) {
        int j0 = __ldg(&adj[p]);
        int j1 = __ldg(&adj[p + 1]);
        int j2 = __ldg(&adj[p + 2]);
        int j3 = __ldg(&adj[p + 3]);
        acc_row(ht4, j0, lane, aA, aB);
        acc_row(ht4, j1, lane, aA, aB);
        acc_row(ht4, j2, lane, aA, aB);
        acc_row(ht4, j3, lane, aA, aB);
    }
    for (; p < e; ++p) acc_row(ht4, __ldg(&adj[p]), lane, aA, aB);

    float di = __ldg(&dinv[i]);
    float4 bb = ((const float4*)bias)[lane];
    float v0 = aA.x * di + bb.x;
    float v1 = aA.y * di + bb.y;
    float v2 = aB.x * di + bb.z;
    float v3 = aB.y * di + bb.w;

    float mu = warp_sum((v0 + v1) + (v2 + v3)) * (1.0f / 128.0f);
    float d0 = v0 - mu, d1 = v1 - mu, d2 = v2 - mu, d3 = v3 - mu;
    float var = warp_sum((d0 * d0 + d1 * d1) + (d2 * d2 + d3 * d3)) * (1.0f / 128.0f);
    float rs = rsqrtf(var + 1e-5f);
    float4 gg = ((const float4*)gamma)[lane];
    float4 be = ((const float4*)beta)[lane];
    float4 o = make_float4(fmaxf(d0 * rs * gg.x + be.x, 0.0f),
                           fmaxf(d1 * rs * gg.y + be.y, 0.0f),
                           fmaxf(d2 * rs * gg.z + be.z, 0.0f),
                           fmaxf(d3 * rs * gg.w + be.w, 0.0f));
    store4(out, i, lane, o);
}

// ---------------- launch (R14-proven schedule) ----------------
extern "C" void kernel_launch(void* const* d_in, const int* in_sizes, int n_in,
                              void* d_out, int out_size) {
    const float* x     = (const float*)d_in[0];
    const int*   edges = (const int*)d_in[1];
    const float* W1    = (const float*)d_in[2];
    const float* b1    = (const float*)d_in[3];
    const float* g1    = (const float*)d_in[4];
    const float* be1   = (const float*)d_in[5];
    const float* W2    = (const float*)d_in[6];
    const float* b2    = (const float*)d_in[7];
    const float* g2    = (const float*)d_in[8];
    const float* be2   = (const float*)d_in[9];
    float* out = (float*)d_out;

    int n = in_sizes[0] / HID;
    int E = in_sizes[1] / 2;
    const int* src = edges;
    const int* dst = edges + E;

    int *deg, *off, *cursor, *adj, *base;
    float *dinv;
    __half *ht, *act;
    unsigned short *whi1, *wlo1, *whi2, *wlo2;
    cudaGetSymbolAddress((void**)&deg, g_deg);
    cudaGetSymbolAddress((void**)&off, g_off);
    cudaGetSymbolAddress((void**)&cursor, g_cursor);
    cudaGetSymbolAddress((void**)&adj, g_adj);
    cudaGetSymbolAddress((void**)&base, g_base);
    cudaGetSymbolAddress((void**)&dinv, g_dinv);
    cudaGetSymbolAddress((void**)&ht, g_ht);
    cudaGetSymbolAddress((void**)&act, g_act);
    cudaGetSymbolAddress((void**)&whi1, g_Whi1);
    cudaGetSymbolAddress((void**)&wlo1, g_Wlo1);
    cudaGetSymbolAddress((void**)&whi2, g_Whi2);
    cudaGetSymbolAddress((void**)&wlo2, g_Wlo2);

    static bool attr_done = false;
    if (!attr_done) {
        cudaFuncSetAttribute(k_gemm_mma<float>, cudaFuncAttributeMaxDynamicSharedMemorySize, GEMM_SMEM);
        cudaFuncSetAttribute(k_gemm_mma<__half>, cudaFuncAttributeMaxDynamicSharedMemorySize, GEMM_SMEM);
        attr_done = true;
    }

    int nbN  = (n + 255) / 256;
    int nbE  = (E + 255) / 256;
    int nbE4 = ((E + 3) / 4 + 255) / 256;
    int nbG  = (n + 63) / 64;
    int nbA  = (n + 7) / 8;

    k_setup<<<256, 256>>>(W1, whi1, wlo1, W2, whi2, wlo2, deg, base, n);
    k_count4<<<nbE4, 256>>>(dst, deg, E);
    k_assign<<<nbN, 256>>>(deg, off, cursor, dinv, base, n);

    bool fork = (g_s2 && g_ev0 && g_ev1);
    if (fork) {
        cudaEventRecord(g_ev0, 0);
        cudaStreamWaitEvent(g_s2, g_ev0, 0);
        k_fill_adj<<<nbE, 256, 0, g_s2>>>(src, dst, cursor, adj, E);
        k_gemm_mma<float><<<nbG, 256, GEMM_SMEM>>>(x, whi1, wlo1, dinv, ht, n);
        cudaEventRecord(g_ev1, g_s2);
        cudaStreamWaitEvent((cudaStream_t)0, g_ev1, 0);
    } else {
        k_fill_adj<<<nbE, 256>>>(src, dst, cursor, adj, E);
        k_gemm_mma<float><<<nbG, 256, GEMM_SMEM>>>(x, whi1, wlo1, dinv, ht, n);
    }

    k_agg_ln<__half><<<nbA, 256>>>((const uint2*)ht, adj, off, deg, dinv, b1, g1, be1, act, n);
    k_gemm_mma<__half><<<nbG, 256, GEMM_SMEM>>>(act, whi2, wlo2, dinv, ht, n);
    k_agg_ln<float><<<nbA, 256>>>((const uint2*)ht, adj, off, deg, dinv, b2, g2, be2, out, n);
}